// round 13
// baseline (speedup 1.0000x reference)
#include <cuda_runtime.h>
#include <math.h>

#define NRAYS 4096
#define NS 64
#define SS 128

// ---------------- scratch (static device globals; no runtime allocation) ---
__device__ float g_Wf[64 * 64];      // W2[:,1:] @ Wc1[9:,:]
__device__ float g_bc1p[64];         // bc1 + b2[1:] @ Wc1[9:,:]
__device__ float g_zmid[NRAYS * SS];
__device__ float g_deltas[NRAYS * SS];
__device__ float g_alpha[NRAYS * SS];
__device__ float g_color[NRAYS * SS * 3];

__device__ __forceinline__ float sigm(float x) {
    if (x >= 0.f) { return 1.f / (1.f + expf(-x)); }
    float e = expf(x);
    return e / (1.f + e);
}

// ---------------- K0: fold feature path into color MLP ---------------------
__global__ void k_prep(const float* __restrict__ W2, const float* __restrict__ b2,
                       const float* __restrict__ Wc1, const float* __restrict__ bc1) {
    int j = blockIdx.x;   // 0..63 hidden unit
    int m = threadIdx.x;  // 0..63 color hidden unit
    float acc = 0.f;
#pragma unroll 8
    for (int k = 0; k < 64; k++)
        acc = fmaf(W2[j * 65 + 1 + k], Wc1[(9 + k) * 64 + m], acc);
    g_Wf[j * 64 + m] = acc;
    if (j == 0) {
        float b = bc1[m];
        for (int k = 0; k < 64; k++)
            b = fmaf(b2[1 + k], Wc1[(9 + k) * 64 + m], b);
        g_bc1p[m] = b;
    }
}

// ---------------- K1: coarse pass + importance sampling + sort -------------
__global__ __launch_bounds__(128) void k_coarse(
    const float* __restrict__ ro_all, const float* __restrict__ rd_all,
    const float* __restrict__ W1, const float* __restrict__ b1,
    const float* __restrict__ W2, const float* __restrict__ b2) {
    int ray = blockIdx.x;
    int tid = threadIdx.x;

    __shared__ float sW1[192], sB1[64], sW2c0[64];
    __shared__ float zv[NS], sdfc[NS], sal[NS - 1], warr[NS - 1], cdf[NS];
    __shared__ float zall[SS], zs[SS];

    for (int i = tid; i < 192; i += 128) sW1[i] = W1[i];
    if (tid < 64) { sB1[tid] = b1[tid]; sW2c0[tid] = W2[tid * 65]; }

    float ro0 = ro_all[ray * 3 + 0], ro1 = ro_all[ray * 3 + 1], ro2 = ro_all[ray * 3 + 2];
    float rd0 = rd_all[ray * 3 + 0], rd1 = rd_all[ray * 3 + 1], rd2 = rd_all[ray * 3 + 2];
    float b20 = b2[0];

    float near = -3.4e38f, far = 3.4e38f;
    {
        float r = rd0 + 1e-15f; float t1 = (-1.f - ro0) / r, t2 = (1.f - ro0) / r;
        near = fmaxf(near, fminf(t1, t2)); far = fminf(far, fmaxf(t1, t2));
    }
    {
        float r = rd1 + 1e-15f; float t1 = (-1.f - ro1) / r, t2 = (1.f - ro1) / r;
        near = fmaxf(near, fminf(t1, t2)); far = fminf(far, fmaxf(t1, t2));
    }
    {
        float r = rd2 + 1e-15f; float t1 = (-1.f - ro2) / r, t2 = (1.f - ro2) / r;
        near = fmaxf(near, fminf(t1, t2)); far = fminf(far, fmaxf(t1, t2));
    }
    near = fmaxf(near, 0.05f);
    __syncthreads();

    // coarse sdf: 64 samples, one per thread (sdf = h @ W2[:,0] + b2[0])
    if (tid < NS) {
        float z = near + (far - near) * ((float)tid * (1.0f / 63.0f));
        zv[tid] = z;
        float x0 = fminf(fmaxf(ro0 + rd0 * z, -1.f), 1.f);
        float x1 = fminf(fmaxf(ro1 + rd1 * z, -1.f), 1.f);
        float x2 = fminf(fmaxf(ro2 + rd2 * z, -1.f), 1.f);
        float sacc = b20;
#pragma unroll 8
        for (int j = 0; j < 64; j++) {
            float p = sB1[j] + x0 * sW1[j] + x1 * sW1[64 + j] + x2 * sW1[128 + j];
            sacc = fmaf(fmaxf(p, 0.f), sW2c0[j], sacc);
        }
        sdfc[tid] = sacc;
    }
    __syncthreads();

    // coarse alpha over 63 intervals
    if (tid < NS - 1) {
        float d = zv[tid + 1] - zv[tid];
        float mid = 0.5f * (sdfc[tid + 1] + sdfc[tid]);
        float cv = (sdfc[tid + 1] - sdfc[tid]) / (d + 1e-5f);
        cv = fminf(fmaxf(cv, -1000.f), 0.f);
        float pc = sigm((mid - cv * d * 0.5f) * 64.f);
        float nc = sigm((mid + cv * d * 0.5f) * 64.f);
        float a = (pc - nc + 1e-5f) / (pc + 1e-5f);
        sal[tid] = fminf(fmaxf(a, 0.f), 1.f);
    }
    __syncthreads();

    // sequential weights + cdf (matches reference cumprod/cumsum semantics)
    if (tid == 0) {
        float cum = 1.f, wsum = 0.f;
        for (int i = 0; i < NS - 1; i++) {
            float wi = sal[i] * cum;
            cum *= (1.f - sal[i] + 1e-7f);
            wi += 1e-5f;
            warr[i] = wi;
            wsum += wi;
        }
        float run = 0.f;
        cdf[0] = 0.f;
        for (int i = 0; i < NS - 1; i++) { run += warr[i] / wsum; cdf[i + 1] = run; }
    }
    __syncthreads();

    // sample_pdf: 64 u values, searchsorted-right + linear interp
    if (tid < NS) {
        float u = (1.0f + 2.0f * (float)tid) * (1.0f / 128.0f);
        int idx = 0;
        for (int j = 0; j < NS; j++) idx += (cdf[j] <= u) ? 1 : 0;
        int below = idx - 1; below = below < 0 ? 0 : (below > 63 ? 63 : below);
        int above = idx > 63 ? 63 : idx;
        float cb = cdf[below], ca = cdf[above];
        float bb = zv[below], ba = zv[above];
        float den = ca - cb;
        if (den < 1e-5f) den = 1.f;
        float tt = (u - cb) / den;
        zall[tid] = zv[tid];
        zall[64 + tid] = bb + tt * (ba - bb);
    }
    __syncthreads();

    // stable rank sort of 128 merged z values
    {
        float v = zall[tid];
        int rank = 0;
        for (int j = 0; j < SS; j++) {
            float o = zall[j];
            rank += (o < v || (o == v && j < tid)) ? 1 : 0;
        }
        zs[rank] = v;
    }
    __syncthreads();

    float sdist = (far - near) * (1.0f / 64.0f);
    float d = (tid < SS - 1) ? (zs[tid + 1] - zs[tid]) : sdist;
    float zm = (tid < SS - 1) ? (zs[tid] + 0.5f * d) : zs[SS - 1];
    g_zmid[ray * SS + tid] = zm;
    g_deltas[ray * SS + tid] = d;
}

// ---------------- K2: fine pass (SDF + FD grad + fused color MLP + alpha) --
__global__ __launch_bounds__(128) void k_fine(
    const float* __restrict__ ro_all, const float* __restrict__ rd_all,
    const float* __restrict__ W1, const float* __restrict__ b1,
    const float* __restrict__ W2, const float* __restrict__ b2,
    const float* __restrict__ Wc1, const float* __restrict__ Wc2,
    const float* __restrict__ bc2, const float* __restrict__ invs) {
    int ray = blockIdx.x;
    int tid = threadIdx.x;

    __shared__ __align__(16) float sWf[4096];
    __shared__ __align__(16) float sWc1a[576];
    __shared__ __align__(16) float sBc1p[64];
    __shared__ float sW1[192], sB1[64], sW2c0[64], sWc2[192];

    for (int i = tid; i < 4096; i += 128) sWf[i] = g_Wf[i];
    for (int i = tid; i < 576; i += 128) sWc1a[i] = Wc1[i];
    for (int i = tid; i < 192; i += 128) { sW1[i] = W1[i]; sWc2[i] = Wc2[i]; }
    if (tid < 64) { sB1[tid] = b1[tid]; sW2c0[tid] = W2[tid * 65]; sBc1p[tid] = g_bc1p[tid]; }

    float ro0 = ro_all[ray * 3 + 0], ro1 = ro_all[ray * 3 + 1], ro2 = ro_all[ray * 3 + 2];
    float rd0 = rd_all[ray * 3 + 0], rd1 = rd_all[ray * 3 + 1], rd2 = rd_all[ray * 3 + 2];
    float b20 = b2[0];
    float inv_s = expf(10.f * invs[0]);
    __syncthreads();

    float zm = g_zmid[ray * SS + tid];
    float dlt = g_deltas[ray * SS + tid];
    float x0 = fminf(fmaxf(ro0 + rd0 * zm, -1.f), 1.f);
    float x1 = fminf(fmaxf(ro1 + rd1 * zm, -1.f), 1.f);
    float x2 = fminf(fmaxf(ro2 + rd2 * zm, -1.f), 1.f);

    // hidden pre-activations + sdf + 6 FD sdf accumulations, one pass
    float pre[64];
    float sa = 0.f, p0 = 0.f, m0 = 0.f, p1 = 0.f, m1 = 0.f, p2 = 0.f, m2 = 0.f;
#pragma unroll
    for (int j = 0; j < 64; j++) {
        float w0 = sW1[j], w1 = sW1[64 + j], w2v = sW1[128 + j];
        float pr = sB1[j] + x0 * w0 + x1 * w1 + x2 * w2v;
        float wc = sW2c0[j];
        sa = fmaf(fmaxf(pr, 0.f), wc, sa);
        float e0 = 0.005f * w0, e1 = 0.005f * w1, e2 = 0.005f * w2v;
        p0 = fmaf(fmaxf(pr + e0, 0.f), wc, p0);
        m0 = fmaf(fmaxf(pr - e0, 0.f), wc, m0);
        p1 = fmaf(fmaxf(pr + e1, 0.f), wc, p1);
        m1 = fmaf(fmaxf(pr - e1, 0.f), wc, m1);
        p2 = fmaf(fmaxf(pr + e2, 0.f), wc, p2);
        m2 = fmaf(fmaxf(pr - e2, 0.f), wc, m2);
        pre[j] = fmaxf(pr, 0.f);  // h = relu(pre), kept for color MLP
    }
    float sdf = sa + b20;
    float g0 = (p0 - m0) / (2.0f * 0.005f);
    float g1 = (p1 - m1) / (2.0f * 0.005f);
    float g2 = (p2 - m2) / (2.0f * 0.005f);
    float nrm = sqrtf(g0 * g0 + g1 * g1 + g2 * g2);
    float inv = 1.f / (1e-5f + nrm);
    float n0 = g0 * inv, n1 = g1 * inv, n2 = g2 * inv;

    // alpha (NeuS cdf difference)
    float tc = rd0 * n0 + rd1 * n1 + rd2 * n2;
    float zc = -100.f * tc;
    float splus = fmaxf(zc, 0.f) + log1pf(expf(-fabsf(zc)));
    float iter_cos = -(splus / 100.0f);
    float e = iter_cos * dlt * 0.5f;
    float pcdf = sigm((sdf - e) * inv_s);
    float ncdf = sigm((sdf + e) * inv_s);
    float alpha = (pcdf - ncdf + 1e-5f) / (pcdf + 1e-5f);
    alpha = fminf(fmaxf(alpha, 0.f), 1.f);
    g_alpha[ray * SS + tid] = alpha;

    // fused color MLP: relu(bc1' + [x,d,n]@Wc1[:9] + h@Wf) @ Wc2 + bc2
    float cin9[9] = {x0, x1, x2, rd0, rd1, rd2, n0, n1, n2};
    float c0 = 0.f, c1 = 0.f, c2 = 0.f;
#pragma unroll 1
    for (int m = 0; m < 64; m += 2) {
        float2 bb = *(const float2*)&sBc1p[m];
        float aA = bb.x, aB = bb.y;
#pragma unroll
        for (int t = 0; t < 9; t++) {
            float2 w = *(const float2*)&sWc1a[t * 64 + m];
            aA = fmaf(cin9[t], w.x, aA);
            aB = fmaf(cin9[t], w.y, aB);
        }
#pragma unroll
        for (int j = 0; j < 64; j++) {
            float2 w = *(const float2*)&sWf[j * 64 + m];
            aA = fmaf(pre[j], w.x, aA);
            aB = fmaf(pre[j], w.y, aB);
        }
        aA = fmaxf(aA, 0.f);
        aB = fmaxf(aB, 0.f);
        c0 = fmaf(aA, sWc2[m * 3 + 0], c0);
        c1 = fmaf(aA, sWc2[m * 3 + 1], c1);
        c2 = fmaf(aA, sWc2[m * 3 + 2], c2);
        c0 = fmaf(aB, sWc2[m * 3 + 3], c0);
        c1 = fmaf(aB, sWc2[m * 3 + 4], c1);
        c2 = fmaf(aB, sWc2[m * 3 + 5], c2);
    }
    int base = (ray * SS + tid) * 3;
    g_color[base + 0] = sigm(c0 + bc2[0]);
    g_color[base + 1] = sigm(c1 + bc2[1]);
    g_color[base + 2] = sigm(c2 + bc2[2]);
}

// ---------------- K3: per-ray compositing -----------------------------------
__global__ __launch_bounds__(128) void k_comp(float* __restrict__ out) {
    int ray = blockIdx.x;
    int t = threadIdx.x;
    __shared__ float sa[SS], sw[SS];
    __shared__ float r0[SS], r1[SS], r2[SS], r3[SS];

    float a = g_alpha[ray * SS + t];
    sa[t] = a;
    int base = (ray * SS + t) * 3;
    float c0 = g_color[base + 0];
    float c1 = g_color[base + 1];
    float c2 = g_color[base + 2];
    __syncthreads();

    if (t == 0) {
        float T = 1.f;
        for (int i = 0; i < SS; i++) {
            sw[i] = sa[i] * T;
            T *= (1.f - sa[i] + 1e-7f);
        }
    }
    __syncthreads();

    float w = sw[t];
    r0[t] = w * c0; r1[t] = w * c1; r2[t] = w * c2; r3[t] = w;
    __syncthreads();
    for (int off = 64; off > 0; off >>= 1) {
        if (t < off) {
            r0[t] += r0[t + off];
            r1[t] += r1[t + off];
            r2[t] += r2[t + off];
            r3[t] += r3[t + off];
        }
        __syncthreads();
    }
    if (t == 0) {
        float bg = 1.f - r3[0];
        out[ray * 3 + 0] = r0[0] + bg;
        out[ray * 3 + 1] = r1[0] + bg;
        out[ray * 3 + 2] = r2[0] + bg;
    }
}

// ---------------- launch -----------------------------------------------------
extern "C" void kernel_launch(void* const* d_in, const int* in_sizes, int n_in,
                              void* d_out, int out_size) {
    const float* ro  = (const float*)d_in[0];
    const float* rd  = (const float*)d_in[1];
    const float* W1  = (const float*)d_in[2];
    const float* b1  = (const float*)d_in[3];
    const float* W2  = (const float*)d_in[4];
    const float* b2  = (const float*)d_in[5];
    const float* Wc1 = (const float*)d_in[6];
    const float* bc1 = (const float*)d_in[7];
    const float* Wc2 = (const float*)d_in[8];
    const float* bc2 = (const float*)d_in[9];
    const float* invs = (const float*)d_in[10];

    int R = in_sizes[0] / 3;
    if (R > NRAYS) R = NRAYS;

    k_prep<<<64, 64>>>(W2, b2, Wc1, bc1);
    k_coarse<<<R, 128>>>(ro, rd, W1, b1, W2, b2);
    k_fine<<<R, 128>>>(ro, rd, W1, b1, W2, b2, Wc1, Wc2, bc2, invs);
    k_comp<<<R, 128>>>((float*)d_out);
}

// round 15
// speedup vs baseline: 1.1698x; 1.1698x over previous
#include <cuda_runtime.h>
#include <math.h>

#define NRAYS 4096
#define NS 64
#define SS 128

// ---------------- scratch (static device globals; no runtime allocation) ---
__device__ float g_WfT[64 * 64];     // transposed folded feature weights: [m][j]
__device__ float g_bc1p[64];         // bc1 + b2[1:] @ Wc1[9:,:]
__device__ float g_V[64 * 12];       // per-j sdf/FD table: {w0,w1,w2,b1},{2e0,2e1,2e2,wc},{wc*sgn(w0..2),0}
__device__ float g_CW[64 * 12];      // per-m color table: Wc1 rows 0..8, bc1p, pad
__device__ float g_Wc2v[64 * 4];     // per-m {wc2_0, wc2_1, wc2_2, 0}
__device__ float g_zmid[NRAYS * SS];
__device__ float g_deltas[NRAYS * SS];

__device__ __forceinline__ float sigm(float x) {
    if (x >= 0.f) { return 1.f / (1.f + expf(-x)); }
    float e = expf(x);
    return e / (1.f + e);
}

__device__ __forceinline__ unsigned long long pk(float lo, float hi) {
    unsigned long long r;
    asm("mov.b64 %0, {%1,%2};" : "=l"(r) : "f"(lo), "f"(hi));
    return r;
}
__device__ __forceinline__ float2 upk(unsigned long long v) {
    float2 f;
    asm("mov.b64 {%0,%1}, %2;" : "=f"(f.x), "=f"(f.y) : "l"(v));
    return f;
}
#define FMA2(d, a, b, c) asm("fma.rn.f32x2 %0, %1, %2, %3;" : "=l"(d) : "l"(a), "l"(b), "l"(c))

// ---------------- K_prep1: fold feature path, transposed Wf + bc1' ---------
__global__ void k_prep1(const float* __restrict__ W2, const float* __restrict__ b2,
                        const float* __restrict__ Wc1, const float* __restrict__ bc1) {
    int m = blockIdx.x;   // 0..63 color hidden unit
    int j = threadIdx.x;  // 0..63 sdf hidden unit
    float acc = 0.f;
#pragma unroll 8
    for (int k = 0; k < 64; k++)
        acc = fmaf(W2[j * 65 + 1 + k], Wc1[(9 + k) * 64 + m], acc);
    g_WfT[m * 64 + j] = acc;
    if (j == 0) {
        float b = bc1[m];
        for (int k = 0; k < 64; k++)
            b = fmaf(b2[1 + k], Wc1[(9 + k) * 64 + m], b);
        g_bc1p[m] = b;
    }
}

// ---------------- K_prep2: per-unit operand tables --------------------------
__global__ void k_prep2(const float* __restrict__ W1, const float* __restrict__ b1,
                        const float* __restrict__ W2, const float* __restrict__ Wc1,
                        const float* __restrict__ Wc2) {
    int i = threadIdx.x;  // 0..63
    // sdf/FD table (row i = hidden unit j)
    float w0 = W1[i], w1 = W1[64 + i], w2v = W1[128 + i];
    float wc = W2[i * 65];
    float* V = &g_V[i * 12];
    V[0] = w0; V[1] = w1; V[2] = w2v; V[3] = b1[i];
    V[4] = 0.01f * fabsf(w0); V[5] = 0.01f * fabsf(w1); V[6] = 0.01f * fabsf(w2v); V[7] = wc;
    // FIX (round-14 bug): need wc * sign(w), NOT copysignf(wc, w) = |wc|*sign(w).
    V[8]  = (w0  < 0.f) ? -wc : wc;
    V[9]  = (w1  < 0.f) ? -wc : wc;
    V[10] = (w2v < 0.f) ? -wc : wc;
    V[11] = 0.f;
    // color table (row i = color hidden unit m)
    float* C = &g_CW[i * 12];
#pragma unroll
    for (int t = 0; t < 9; t++) C[t] = Wc1[t * 64 + i];
    C[9] = g_bc1p[i]; C[10] = 0.f; C[11] = 0.f;
    g_Wc2v[i * 4 + 0] = Wc2[i * 3 + 0];
    g_Wc2v[i * 4 + 1] = Wc2[i * 3 + 1];
    g_Wc2v[i * 4 + 2] = Wc2[i * 3 + 2];
    g_Wc2v[i * 4 + 3] = 0.f;
}

// ---------------- K1: coarse pass + importance sampling + merge ------------
__global__ __launch_bounds__(128) void k_coarse(
    const float* __restrict__ ro_all, const float* __restrict__ rd_all,
    const float* __restrict__ b2) {
    int ray = blockIdx.x;
    int tid = threadIdx.x;

    __shared__ __align__(16) float sV[768];
    __shared__ float zv[NS], sdfc[NS], sal[NS - 1], warr[NS - 1], cdf[NS];
    __shared__ float zn[NS], zs[SS], part[128];

    for (int i = tid; i < 768; i += 128) sV[i] = g_V[i];

    float ro0 = ro_all[ray * 3 + 0], ro1 = ro_all[ray * 3 + 1], ro2 = ro_all[ray * 3 + 2];
    float rd0 = rd_all[ray * 3 + 0], rd1 = rd_all[ray * 3 + 1], rd2 = rd_all[ray * 3 + 2];
    float b20 = b2[0];

    float near = -3.4e38f, far = 3.4e38f;
    {
        float r = rd0 + 1e-15f; float t1 = (-1.f - ro0) / r, t2 = (1.f - ro0) / r;
        near = fmaxf(near, fminf(t1, t2)); far = fminf(far, fmaxf(t1, t2));
    }
    {
        float r = rd1 + 1e-15f; float t1 = (-1.f - ro1) / r, t2 = (1.f - ro1) / r;
        near = fmaxf(near, fminf(t1, t2)); far = fminf(far, fmaxf(t1, t2));
    }
    {
        float r = rd2 + 1e-15f; float t1 = (-1.f - ro2) / r, t2 = (1.f - ro2) / r;
        near = fmaxf(near, fminf(t1, t2)); far = fminf(far, fmaxf(t1, t2));
    }
    near = fmaxf(near, 0.05f);
    __syncthreads();

    // coarse sdf: 64 samples x 2 half-sums (all 128 threads active)
    {
        int s = tid & 63;
        int j0 = (tid >> 6) * 32;
        float z = near + (far - near) * ((float)s * (1.0f / 63.0f));
        if (tid < NS) zv[tid] = near + (far - near) * ((float)tid * (1.0f / 63.0f));
        float x0 = fminf(fmaxf(ro0 + rd0 * z, -1.f), 1.f);
        float x1 = fminf(fmaxf(ro1 + rd1 * z, -1.f), 1.f);
        float x2 = fminf(fmaxf(ro2 + rd2 * z, -1.f), 1.f);
        float acc = 0.f;
#pragma unroll 8
        for (int j = j0; j < j0 + 32; j++) {
            const float4* vr = (const float4*)&sV[j * 12];
            float4 a = vr[0];
            float wc = sV[j * 12 + 7];
            float p = fmaf(x2, a.z, fmaf(x1, a.y, fmaf(x0, a.x, a.w)));
            acc = fmaf(fmaxf(p, 0.f), wc, acc);
        }
        part[tid] = acc;
    }
    __syncthreads();
    if (tid < NS) sdfc[tid] = part[tid] + part[64 + tid] + b20;
    __syncthreads();

    // coarse alpha over 63 intervals
    if (tid < NS - 1) {
        float d = zv[tid + 1] - zv[tid];
        float mid = 0.5f * (sdfc[tid + 1] + sdfc[tid]);
        float cv = (sdfc[tid + 1] - sdfc[tid]) / (d + 1e-5f);
        cv = fminf(fmaxf(cv, -1000.f), 0.f);
        float pc = sigm((mid - cv * d * 0.5f) * 64.f);
        float nc = sigm((mid + cv * d * 0.5f) * 64.f);
        float a = (pc - nc + 1e-5f) / (pc + 1e-5f);
        sal[tid] = fminf(fmaxf(a, 0.f), 1.f);
    }
    __syncthreads();

    // sequential weights + cdf (matches reference cumprod/cumsum semantics)
    if (tid == 0) {
        float cum = 1.f, wsum = 0.f;
        for (int i = 0; i < NS - 1; i++) {
            float wi = sal[i] * cum;
            cum *= (1.f - sal[i] + 1e-7f);
            wi += 1e-5f;
            warr[i] = wi;
            wsum += wi;
        }
        float inv = 1.f / wsum;
        float run = 0.f;
        cdf[0] = 0.f;
        for (int i = 0; i < NS - 1; i++) { run += warr[i] * inv; cdf[i + 1] = run; }
    }
    __syncthreads();

    // sample_pdf: 64 u values, binary searchsorted-right + linear interp
    if (tid < NS) {
        float u = (1.0f + 2.0f * (float)tid) * (1.0f / 128.0f);
        int lo = 0, hi = NS;
        while (lo < hi) { int mid = (lo + hi) >> 1; if (cdf[mid] <= u) lo = mid + 1; else hi = mid; }
        int idx = lo;
        int below = idx - 1; below = below < 0 ? 0 : (below > 63 ? 63 : below);
        int above = idx > 63 ? 63 : idx;
        float cb = cdf[below], ca = cdf[above];
        float bb = zv[below], ba = zv[above];
        float den = ca - cb;
        if (den < 1e-5f) den = 1.f;
        float tt = (u - cb) / den;
        zn[tid] = bb + tt * (ba - bb);
    }
    __syncthreads();

    // merge of two sorted length-64 arrays (zv first on ties) via binary search
    {
        float v; int rank;
        if (tid < NS) {
            v = zv[tid];
            int lo = 0, hi = NS;
            while (lo < hi) { int mid = (lo + hi) >> 1; if (zn[mid] < v) lo = mid + 1; else hi = mid; }
            rank = tid + lo;
        } else {
            int t = tid - NS;
            v = zn[t];
            int lo = 0, hi = NS;
            while (lo < hi) { int mid = (lo + hi) >> 1; if (zv[mid] <= v) lo = mid + 1; else hi = mid; }
            rank = t + lo;
        }
        zs[rank] = v;
    }
    __syncthreads();

    float sdist = (far - near) * (1.0f / 64.0f);
    float d = (tid < SS - 1) ? (zs[tid + 1] - zs[tid]) : sdist;
    float zm = (tid < SS - 1) ? (zs[tid] + 0.5f * d) : zs[SS - 1];
    g_zmid[ray * SS + tid] = zm;
    g_deltas[ray * SS + tid] = d;
}

// ---------------- K2: fine pass + fused compositing -------------------------
__global__ __launch_bounds__(128, 4) void k_fine(
    const float* __restrict__ ro_all, const float* __restrict__ rd_all,
    const float* __restrict__ b2, const float* __restrict__ bc2,
    const float* __restrict__ invs, float* __restrict__ out) {
    int ray = blockIdx.x;
    int tid = threadIdx.x;
    int lane = tid & 31, warp = tid >> 5;

    __shared__ __align__(16) float sWfT[4096];
    __shared__ __align__(16) float sV[768];
    __shared__ __align__(16) float sCW[768];
    __shared__ __align__(16) float4 sWc2v[64];
    __shared__ float swt[4];
    __shared__ float sred[4][4];

    for (int i = tid; i < 4096; i += 128) sWfT[i] = g_WfT[i];
    for (int i = tid; i < 768; i += 128) { sV[i] = g_V[i]; sCW[i] = g_CW[i]; }
    if (tid < 64) sWc2v[tid] = ((const float4*)g_Wc2v)[tid];

    float ro0 = ro_all[ray * 3 + 0], ro1 = ro_all[ray * 3 + 1], ro2 = ro_all[ray * 3 + 2];
    float rd0 = rd_all[ray * 3 + 0], rd1 = rd_all[ray * 3 + 1], rd2 = rd_all[ray * 3 + 2];
    float b20 = b2[0];
    float inv_s = expf(10.f * invs[0]);
    __syncthreads();

    float zm = g_zmid[ray * SS + tid];
    float dlt = g_deltas[ray * SS + tid];
    float x0 = fminf(fmaxf(ro0 + rd0 * zm, -1.f), 1.f);
    float x1 = fminf(fmaxf(ro1 + rd1 * zm, -1.f), 1.f);
    float x2 = fminf(fmaxf(ro2 + rd2 * zm, -1.f), 1.f);

    // sdf + FD gradient in one pass; relu(pre) packed into pre2[] pairs.
    // relu(pr+e) - relu(pr-e) == sign(e) * min(2|e|, relu(pr+|e|))
    unsigned long long pre2[32];
    float sa = 0.f, ga0 = 0.f, ga1 = 0.f, ga2 = 0.f;
    float hprev = 0.f;
#pragma unroll
    for (int j = 0; j < 64; j++) {
        const float4* vr = (const float4*)&sV[j * 12];
        float4 a = vr[0], b = vr[1], c = vr[2];
        float pr = fmaf(x2, a.z, fmaf(x1, a.y, fmaf(x0, a.x, a.w)));
        float h = fmaxf(pr, 0.f);
        sa = fmaf(h, b.w, sa);
        float t0 = fminf(fmaxf(fmaf(0.5f, b.x, pr), 0.f), b.x);
        float t1 = fminf(fmaxf(fmaf(0.5f, b.y, pr), 0.f), b.y);
        float t2 = fminf(fmaxf(fmaf(0.5f, b.z, pr), 0.f), b.z);
        ga0 = fmaf(t0, c.x, ga0);
        ga1 = fmaf(t1, c.y, ga1);
        ga2 = fmaf(t2, c.z, ga2);
        if (j & 1) pre2[j >> 1] = pk(hprev, h); else hprev = h;
    }
    float sdf = sa + b20;
    float g0 = ga0 * 100.f, g1 = ga1 * 100.f, g2 = ga2 * 100.f;
    float nrm = sqrtf(g0 * g0 + g1 * g1 + g2 * g2);
    float inv = 1.f / (1e-5f + nrm);
    float n0 = g0 * inv, n1 = g1 * inv, n2 = g2 * inv;

    // alpha (NeuS cdf difference)
    float tc = rd0 * n0 + rd1 * n1 + rd2 * n2;
    float zc = -100.f * tc;
    float splus = fmaxf(zc, 0.f) + log1pf(expf(-fabsf(zc)));
    float iter_cos = -(splus / 100.0f);
    float e = iter_cos * dlt * 0.5f;
    float pcdf = sigm((sdf - e) * inv_s);
    float ncdf = sigm((sdf + e) * inv_s);
    float alpha = (pcdf - ncdf + 1e-5f) / (pcdf + 1e-5f);
    alpha = fminf(fmaxf(alpha, 0.f), 1.f);

    // fused color MLP with packed f32x2 FMA, accumulating along j pairs
    unsigned long long cin2[5];
    cin2[0] = pk(x0, x1);
    cin2[1] = pk(x2, rd0);
    cin2[2] = pk(rd1, rd2);
    cin2[3] = pk(n0, n1);
    cin2[4] = pk(n2, 1.f);

    float c0 = 0.f, c1 = 0.f, c2 = 0.f;
#pragma unroll 2
    for (int m = 0; m < 64; m++) {
        const ulonglong2* cw = (const ulonglong2*)&sCW[m * 12];
        ulonglong2 q0 = cw[0], q1 = cw[1];
        unsigned long long q4 = ((const unsigned long long*)&sCW[m * 12])[4];
        unsigned long long acc = 0ull;
        FMA2(acc, cin2[0], q0.x, acc);
        FMA2(acc, cin2[1], q0.y, acc);
        FMA2(acc, cin2[2], q1.x, acc);
        FMA2(acc, cin2[3], q1.y, acc);
        FMA2(acc, cin2[4], q4, acc);
        const ulonglong2* wr = (const ulonglong2*)&sWfT[m * 64];
#pragma unroll
        for (int k = 0; k < 16; k++) {
            ulonglong2 q = wr[k];
            FMA2(acc, pre2[2 * k], q.x, acc);
            FMA2(acc, pre2[2 * k + 1], q.y, acc);
        }
        float2 af = upk(acc);
        float act = fmaxf(af.x + af.y, 0.f);
        float4 w = sWc2v[m];
        c0 = fmaf(act, w.x, c0);
        c1 = fmaf(act, w.y, c1);
        c2 = fmaf(act, w.z, c2);
    }
    float col0 = sigm(c0 + bc2[0]);
    float col1 = sigm(c1 + bc2[1]);
    float col2 = sigm(c2 + bc2[2]);

    // ---- fused compositing: exclusive product scan across 128 samples ----
    float v = 1.f - alpha + 1e-7f;
    float p = v;
#pragma unroll
    for (int d = 1; d < 32; d <<= 1) {
        float t = __shfl_up_sync(0xffffffffu, p, d);
        if (lane >= d) p *= t;
    }
    if (lane == 31) swt[warp] = p;
    __syncthreads();
    float pref = 1.f;
#pragma unroll
    for (int w2 = 0; w2 < 3; w2++)
        if (w2 < warp) pref *= swt[w2];
    float excl = __shfl_up_sync(0xffffffffu, p, 1);
    if (lane == 0) excl = 1.f;
    float T = pref * excl;
    float wgt = alpha * T;

    float s0 = wgt * col0, s1 = wgt * col1, s2 = wgt * col2, s3 = wgt;
#pragma unroll
    for (int d = 16; d > 0; d >>= 1) {
        s0 += __shfl_down_sync(0xffffffffu, s0, d);
        s1 += __shfl_down_sync(0xffffffffu, s1, d);
        s2 += __shfl_down_sync(0xffffffffu, s2, d);
        s3 += __shfl_down_sync(0xffffffffu, s3, d);
    }
    if (lane == 0) {
        sred[warp][0] = s0; sred[warp][1] = s1; sred[warp][2] = s2; sred[warp][3] = s3;
    }
    __syncthreads();
    if (tid == 0) {
        float r0 = sred[0][0] + sred[1][0] + sred[2][0] + sred[3][0];
        float r1 = sred[0][1] + sred[1][1] + sred[2][1] + sred[3][1];
        float r2 = sred[0][2] + sred[1][2] + sred[2][2] + sred[3][2];
        float r3 = sred[0][3] + sred[1][3] + sred[2][3] + sred[3][3];
        float bg = 1.f - r3;
        out[ray * 3 + 0] = r0 + bg;
        out[ray * 3 + 1] = r1 + bg;
        out[ray * 3 + 2] = r2 + bg;
    }
}

// ---------------- launch -----------------------------------------------------
extern "C" void kernel_launch(void* const* d_in, const int* in_sizes, int n_in,
                              void* d_out, int out_size) {
    const float* ro  = (const float*)d_in[0];
    const float* rd  = (const float*)d_in[1];
    const float* W1  = (const float*)d_in[2];
    const float* b1  = (const float*)d_in[3];
    const float* W2  = (const float*)d_in[4];
    const float* b2  = (const float*)d_in[5];
    const float* Wc1 = (const float*)d_in[6];
    const float* bc1 = (const float*)d_in[7];
    const float* Wc2 = (const float*)d_in[8];
    const float* bc2 = (const float*)d_in[9];
    const float* invs = (const float*)d_in[10];

    int R = in_sizes[0] / 3;
    if (R > NRAYS) R = NRAYS;

    k_prep1<<<64, 64>>>(W2, b2, Wc1, bc1);
    k_prep2<<<1, 64>>>(W1, b1, W2, Wc1, Wc2);
    k_coarse<<<R, 128>>>(ro, rd, b2);
    k_fine<<<R, 128>>>(ro, rd, b2, bc2, invs, (float*)d_out);
}

// round 16
// speedup vs baseline: 1.1704x; 1.0005x over previous
#include <cuda_runtime.h>
#include <math.h>

#define NRAYS 4096
#define NS 64
#define SS 128

// ---------------- scratch (static device globals; no runtime allocation) ---
__device__ float g_WfT[64 * 64];     // transposed folded feature weights: [m][j]
__device__ float g_bc1p[64];         // bc1 + b2[1:] @ Wc1[9:,:]
__device__ float g_V[64 * 12];       // per-j sdf/FD table: {w0,w1,w2,b1},{2e0,2e1,2e2,wc},{wc*sgn(w0..2),0}
__device__ float g_CW[64 * 12];      // per-m color table: Wc1 rows 0..8, bc1p, pad
__device__ float g_Wc2v[64 * 4];     // per-m {wc2_0, wc2_1, wc2_2, 0}
__device__ float g_zmid[NRAYS * SS];
__device__ float g_deltas[NRAYS * SS];

__device__ __forceinline__ float sigm(float x) {
    if (x >= 0.f) { return 1.f / (1.f + expf(-x)); }
    float e = expf(x);
    return e / (1.f + e);
}

__device__ __forceinline__ unsigned long long pk(float lo, float hi) {
    unsigned long long r;
    asm("mov.b64 %0, {%1,%2};" : "=l"(r) : "f"(lo), "f"(hi));
    return r;
}
__device__ __forceinline__ float2 upk(unsigned long long v) {
    float2 f;
    asm("mov.b64 {%0,%1}, %2;" : "=f"(f.x), "=f"(f.y) : "l"(v));
    return f;
}
#define FMA2(d, a, b, c) asm("fma.rn.f32x2 %0, %1, %2, %3;" : "=l"(d) : "l"(a), "l"(b), "l"(c))

// ---------------- K_prep1: fold feature path, transposed Wf + bc1' ---------
__global__ void k_prep1(const float* __restrict__ W2, const float* __restrict__ b2,
                        const float* __restrict__ Wc1, const float* __restrict__ bc1) {
    int m = blockIdx.x;   // 0..63 color hidden unit
    int j = threadIdx.x;  // 0..63 sdf hidden unit
    float acc = 0.f;
#pragma unroll 8
    for (int k = 0; k < 64; k++)
        acc = fmaf(W2[j * 65 + 1 + k], Wc1[(9 + k) * 64 + m], acc);
    g_WfT[m * 64 + j] = acc;
    if (j == 0) {
        float b = bc1[m];
        for (int k = 0; k < 64; k++)
            b = fmaf(b2[1 + k], Wc1[(9 + k) * 64 + m], b);
        g_bc1p[m] = b;
    }
}

// ---------------- K_prep2: per-unit operand tables --------------------------
__global__ void k_prep2(const float* __restrict__ W1, const float* __restrict__ b1,
                        const float* __restrict__ W2, const float* __restrict__ Wc1,
                        const float* __restrict__ Wc2) {
    int i = threadIdx.x;  // 0..63
    // sdf/FD table (row i = hidden unit j)
    float w0 = W1[i], w1 = W1[64 + i], w2v = W1[128 + i];
    float wc = W2[i * 65];
    float* V = &g_V[i * 12];
    V[0] = w0; V[1] = w1; V[2] = w2v; V[3] = b1[i];
    V[4] = 0.01f * fabsf(w0); V[5] = 0.01f * fabsf(w1); V[6] = 0.01f * fabsf(w2v); V[7] = wc;
    // FIX (round-14 bug): need wc * sign(w), NOT copysignf(wc, w) = |wc|*sign(w).
    V[8]  = (w0  < 0.f) ? -wc : wc;
    V[9]  = (w1  < 0.f) ? -wc : wc;
    V[10] = (w2v < 0.f) ? -wc : wc;
    V[11] = 0.f;
    // color table (row i = color hidden unit m)
    float* C = &g_CW[i * 12];
#pragma unroll
    for (int t = 0; t < 9; t++) C[t] = Wc1[t * 64 + i];
    C[9] = g_bc1p[i]; C[10] = 0.f; C[11] = 0.f;
    g_Wc2v[i * 4 + 0] = Wc2[i * 3 + 0];
    g_Wc2v[i * 4 + 1] = Wc2[i * 3 + 1];
    g_Wc2v[i * 4 + 2] = Wc2[i * 3 + 2];
    g_Wc2v[i * 4 + 3] = 0.f;
}

// ---------------- K1: coarse pass + importance sampling + merge ------------
__global__ __launch_bounds__(128) void k_coarse(
    const float* __restrict__ ro_all, const float* __restrict__ rd_all,
    const float* __restrict__ b2) {
    int ray = blockIdx.x;
    int tid = threadIdx.x;

    __shared__ __align__(16) float sV[768];
    __shared__ float zv[NS], sdfc[NS], sal[NS - 1], warr[NS - 1], cdf[NS];
    __shared__ float zn[NS], zs[SS], part[128];

    for (int i = tid; i < 768; i += 128) sV[i] = g_V[i];

    float ro0 = ro_all[ray * 3 + 0], ro1 = ro_all[ray * 3 + 1], ro2 = ro_all[ray * 3 + 2];
    float rd0 = rd_all[ray * 3 + 0], rd1 = rd_all[ray * 3 + 1], rd2 = rd_all[ray * 3 + 2];
    float b20 = b2[0];

    float near = -3.4e38f, far = 3.4e38f;
    {
        float r = rd0 + 1e-15f; float t1 = (-1.f - ro0) / r, t2 = (1.f - ro0) / r;
        near = fmaxf(near, fminf(t1, t2)); far = fminf(far, fmaxf(t1, t2));
    }
    {
        float r = rd1 + 1e-15f; float t1 = (-1.f - ro1) / r, t2 = (1.f - ro1) / r;
        near = fmaxf(near, fminf(t1, t2)); far = fminf(far, fmaxf(t1, t2));
    }
    {
        float r = rd2 + 1e-15f; float t1 = (-1.f - ro2) / r, t2 = (1.f - ro2) / r;
        near = fmaxf(near, fminf(t1, t2)); far = fminf(far, fmaxf(t1, t2));
    }
    near = fmaxf(near, 0.05f);
    __syncthreads();

    // coarse sdf: 64 samples x 2 half-sums (all 128 threads active)
    {
        int s = tid & 63;
        int j0 = (tid >> 6) * 32;
        float z = near + (far - near) * ((float)s * (1.0f / 63.0f));
        if (tid < NS) zv[tid] = near + (far - near) * ((float)tid * (1.0f / 63.0f));
        float x0 = fminf(fmaxf(ro0 + rd0 * z, -1.f), 1.f);
        float x1 = fminf(fmaxf(ro1 + rd1 * z, -1.f), 1.f);
        float x2 = fminf(fmaxf(ro2 + rd2 * z, -1.f), 1.f);
        float acc = 0.f;
#pragma unroll 8
        for (int j = j0; j < j0 + 32; j++) {
            const float4* vr = (const float4*)&sV[j * 12];
            float4 a = vr[0];
            float wc = sV[j * 12 + 7];
            float p = fmaf(x2, a.z, fmaf(x1, a.y, fmaf(x0, a.x, a.w)));
            acc = fmaf(fmaxf(p, 0.f), wc, acc);
        }
        part[tid] = acc;
    }
    __syncthreads();
    if (tid < NS) sdfc[tid] = part[tid] + part[64 + tid] + b20;
    __syncthreads();

    // coarse alpha over 63 intervals
    if (tid < NS - 1) {
        float d = zv[tid + 1] - zv[tid];
        float mid = 0.5f * (sdfc[tid + 1] + sdfc[tid]);
        float cv = (sdfc[tid + 1] - sdfc[tid]) / (d + 1e-5f);
        cv = fminf(fmaxf(cv, -1000.f), 0.f);
        float pc = sigm((mid - cv * d * 0.5f) * 64.f);
        float nc = sigm((mid + cv * d * 0.5f) * 64.f);
        float a = (pc - nc + 1e-5f) / (pc + 1e-5f);
        sal[tid] = fminf(fmaxf(a, 0.f), 1.f);
    }
    __syncthreads();

    // sequential weights + cdf (matches reference cumprod/cumsum semantics)
    if (tid == 0) {
        float cum = 1.f, wsum = 0.f;
        for (int i = 0; i < NS - 1; i++) {
            float wi = sal[i] * cum;
            cum *= (1.f - sal[i] + 1e-7f);
            wi += 1e-5f;
            warr[i] = wi;
            wsum += wi;
        }
        float inv = 1.f / wsum;
        float run = 0.f;
        cdf[0] = 0.f;
        for (int i = 0; i < NS - 1; i++) { run += warr[i] * inv; cdf[i + 1] = run; }
    }
    __syncthreads();

    // sample_pdf: 64 u values, binary searchsorted-right + linear interp
    if (tid < NS) {
        float u = (1.0f + 2.0f * (float)tid) * (1.0f / 128.0f);
        int lo = 0, hi = NS;
        while (lo < hi) { int mid = (lo + hi) >> 1; if (cdf[mid] <= u) lo = mid + 1; else hi = mid; }
        int idx = lo;
        int below = idx - 1; below = below < 0 ? 0 : (below > 63 ? 63 : below);
        int above = idx > 63 ? 63 : idx;
        float cb = cdf[below], ca = cdf[above];
        float bb = zv[below], ba = zv[above];
        float den = ca - cb;
        if (den < 1e-5f) den = 1.f;
        float tt = (u - cb) / den;
        zn[tid] = bb + tt * (ba - bb);
    }
    __syncthreads();

    // merge of two sorted length-64 arrays (zv first on ties) via binary search
    {
        float v; int rank;
        if (tid < NS) {
            v = zv[tid];
            int lo = 0, hi = NS;
            while (lo < hi) { int mid = (lo + hi) >> 1; if (zn[mid] < v) lo = mid + 1; else hi = mid; }
            rank = tid + lo;
        } else {
            int t = tid - NS;
            v = zn[t];
            int lo = 0, hi = NS;
            while (lo < hi) { int mid = (lo + hi) >> 1; if (zv[mid] <= v) lo = mid + 1; else hi = mid; }
            rank = t + lo;
        }
        zs[rank] = v;
    }
    __syncthreads();

    float sdist = (far - near) * (1.0f / 64.0f);
    float d = (tid < SS - 1) ? (zs[tid + 1] - zs[tid]) : sdist;
    float zm = (tid < SS - 1) ? (zs[tid] + 0.5f * d) : zs[SS - 1];
    g_zmid[ray * SS + tid] = zm;
    g_deltas[ray * SS + tid] = d;
}

// ---------------- K2: fine pass + fused compositing -------------------------
__global__ __launch_bounds__(128, 4) void k_fine(
    const float* __restrict__ ro_all, const float* __restrict__ rd_all,
    const float* __restrict__ b2, const float* __restrict__ bc2,
    const float* __restrict__ invs, float* __restrict__ out) {
    int ray = blockIdx.x;
    int tid = threadIdx.x;
    int lane = tid & 31, warp = tid >> 5;

    __shared__ __align__(16) float sWfT[4096];
    __shared__ __align__(16) float sV[768];
    __shared__ __align__(16) float sCW[768];
    __shared__ __align__(16) float4 sWc2v[64];
    __shared__ float swt[4];
    __shared__ float sred[4][4];

    for (int i = tid; i < 4096; i += 128) sWfT[i] = g_WfT[i];
    for (int i = tid; i < 768; i += 128) { sV[i] = g_V[i]; sCW[i] = g_CW[i]; }
    if (tid < 64) sWc2v[tid] = ((const float4*)g_Wc2v)[tid];

    float ro0 = ro_all[ray * 3 + 0], ro1 = ro_all[ray * 3 + 1], ro2 = ro_all[ray * 3 + 2];
    float rd0 = rd_all[ray * 3 + 0], rd1 = rd_all[ray * 3 + 1], rd2 = rd_all[ray * 3 + 2];
    float b20 = b2[0];
    float inv_s = expf(10.f * invs[0]);
    __syncthreads();

    float zm = g_zmid[ray * SS + tid];
    float dlt = g_deltas[ray * SS + tid];
    float x0 = fminf(fmaxf(ro0 + rd0 * zm, -1.f), 1.f);
    float x1 = fminf(fmaxf(ro1 + rd1 * zm, -1.f), 1.f);
    float x2 = fminf(fmaxf(ro2 + rd2 * zm, -1.f), 1.f);

    // sdf + FD gradient in one pass; relu(pre) packed into pre2[] pairs.
    // relu(pr+e) - relu(pr-e) == sign(e) * min(2|e|, relu(pr+|e|))
    unsigned long long pre2[32];
    float sa = 0.f, ga0 = 0.f, ga1 = 0.f, ga2 = 0.f;
    float hprev = 0.f;
#pragma unroll
    for (int j = 0; j < 64; j++) {
        const float4* vr = (const float4*)&sV[j * 12];
        float4 a = vr[0], b = vr[1], c = vr[2];
        float pr = fmaf(x2, a.z, fmaf(x1, a.y, fmaf(x0, a.x, a.w)));
        float h = fmaxf(pr, 0.f);
        sa = fmaf(h, b.w, sa);
        float t0 = fminf(fmaxf(fmaf(0.5f, b.x, pr), 0.f), b.x);
        float t1 = fminf(fmaxf(fmaf(0.5f, b.y, pr), 0.f), b.y);
        float t2 = fminf(fmaxf(fmaf(0.5f, b.z, pr), 0.f), b.z);
        ga0 = fmaf(t0, c.x, ga0);
        ga1 = fmaf(t1, c.y, ga1);
        ga2 = fmaf(t2, c.z, ga2);
        if (j & 1) pre2[j >> 1] = pk(hprev, h); else hprev = h;
    }
    float sdf = sa + b20;
    float g0 = ga0 * 100.f, g1 = ga1 * 100.f, g2 = ga2 * 100.f;
    float nrm = sqrtf(g0 * g0 + g1 * g1 + g2 * g2);
    float inv = 1.f / (1e-5f + nrm);
    float n0 = g0 * inv, n1 = g1 * inv, n2 = g2 * inv;

    // alpha (NeuS cdf difference)
    float tc = rd0 * n0 + rd1 * n1 + rd2 * n2;
    float zc = -100.f * tc;
    float splus = fmaxf(zc, 0.f) + log1pf(expf(-fabsf(zc)));
    float iter_cos = -(splus / 100.0f);
    float e = iter_cos * dlt * 0.5f;
    float pcdf = sigm((sdf - e) * inv_s);
    float ncdf = sigm((sdf + e) * inv_s);
    float alpha = (pcdf - ncdf + 1e-5f) / (pcdf + 1e-5f);
    alpha = fminf(fmaxf(alpha, 0.f), 1.f);

    // fused color MLP with packed f32x2 FMA, accumulating along j pairs
    unsigned long long cin2[5];
    cin2[0] = pk(x0, x1);
    cin2[1] = pk(x2, rd0);
    cin2[2] = pk(rd1, rd2);
    cin2[3] = pk(n0, n1);
    cin2[4] = pk(n2, 1.f);

    float c0 = 0.f, c1 = 0.f, c2 = 0.f;
#pragma unroll 2
    for (int m = 0; m < 64; m++) {
        const ulonglong2* cw = (const ulonglong2*)&sCW[m * 12];
        ulonglong2 q0 = cw[0], q1 = cw[1];
        unsigned long long q4 = ((const unsigned long long*)&sCW[m * 12])[4];
        unsigned long long acc = 0ull;
        FMA2(acc, cin2[0], q0.x, acc);
        FMA2(acc, cin2[1], q0.y, acc);
        FMA2(acc, cin2[2], q1.x, acc);
        FMA2(acc, cin2[3], q1.y, acc);
        FMA2(acc, cin2[4], q4, acc);
        const ulonglong2* wr = (const ulonglong2*)&sWfT[m * 64];
#pragma unroll
        for (int k = 0; k < 16; k++) {
            ulonglong2 q = wr[k];
            FMA2(acc, pre2[2 * k], q.x, acc);
            FMA2(acc, pre2[2 * k + 1], q.y, acc);
        }
        float2 af = upk(acc);
        float act = fmaxf(af.x + af.y, 0.f);
        float4 w = sWc2v[m];
        c0 = fmaf(act, w.x, c0);
        c1 = fmaf(act, w.y, c1);
        c2 = fmaf(act, w.z, c2);
    }
    float col0 = sigm(c0 + bc2[0]);
    float col1 = sigm(c1 + bc2[1]);
    float col2 = sigm(c2 + bc2[2]);

    // ---- fused compositing: exclusive product scan across 128 samples ----
    float v = 1.f - alpha + 1e-7f;
    float p = v;
#pragma unroll
    for (int d = 1; d < 32; d <<= 1) {
        float t = __shfl_up_sync(0xffffffffu, p, d);
        if (lane >= d) p *= t;
    }
    if (lane == 31) swt[warp] = p;
    __syncthreads();
    float pref = 1.f;
#pragma unroll
    for (int w2 = 0; w2 < 3; w2++)
        if (w2 < warp) pref *= swt[w2];
    float excl = __shfl_up_sync(0xffffffffu, p, 1);
    if (lane == 0) excl = 1.f;
    float T = pref * excl;
    float wgt = alpha * T;

    float s0 = wgt * col0, s1 = wgt * col1, s2 = wgt * col2, s3 = wgt;
#pragma unroll
    for (int d = 16; d > 0; d >>= 1) {
        s0 += __shfl_down_sync(0xffffffffu, s0, d);
        s1 += __shfl_down_sync(0xffffffffu, s1, d);
        s2 += __shfl_down_sync(0xffffffffu, s2, d);
        s3 += __shfl_down_sync(0xffffffffu, s3, d);
    }
    if (lane == 0) {
        sred[warp][0] = s0; sred[warp][1] = s1; sred[warp][2] = s2; sred[warp][3] = s3;
    }
    __syncthreads();
    if (tid == 0) {
        float r0 = sred[0][0] + sred[1][0] + sred[2][0] + sred[3][0];
        float r1 = sred[0][1] + sred[1][1] + sred[2][1] + sred[3][1];
        float r2 = sred[0][2] + sred[1][2] + sred[2][2] + sred[3][2];
        float r3 = sred[0][3] + sred[1][3] + sred[2][3] + sred[3][3];
        float bg = 1.f - r3;
        out[ray * 3 + 0] = r0 + bg;
        out[ray * 3 + 1] = r1 + bg;
        out[ray * 3 + 2] = r2 + bg;
    }
}

// ---------------- launch -----------------------------------------------------
extern "C" void kernel_launch(void* const* d_in, const int* in_sizes, int n_in,
                              void* d_out, int out_size) {
    const float* ro  = (const float*)d_in[0];
    const float* rd  = (const float*)d_in[1];
    const float* W1  = (const float*)d_in[2];
    const float* b1  = (const float*)d_in[3];
    const float* W2  = (const float*)d_in[4];
    const float* b2  = (const float*)d_in[5];
    const float* Wc1 = (const float*)d_in[6];
    const float* bc1 = (const float*)d_in[7];
    const float* Wc2 = (const float*)d_in[8];
    const float* bc2 = (const float*)d_in[9];
    const float* invs = (const float*)d_in[10];

    int R = in_sizes[0] / 3;
    if (R > NRAYS) R = NRAYS;

    k_prep1<<<64, 64>>>(W2, b2, Wc1, bc1);
    k_prep2<<<1, 64>>>(W1, b1, W2, Wc1, Wc2);
    k_coarse<<<R, 128>>>(ro, rd, b2);
    k_fine<<<R, 128>>>(ro, rd, b2, bc2, invs, (float*)d_out);
}